// round 8
// baseline (speedup 1.0000x reference)
#include <cuda_runtime.h>

#define BB 4
#define ROI 90
#define TT 200
#define HH 3
#define FF 96
#define G3 288
#define NB 12   // BB*HH
#define SEQ_GROUPS 3
#define SEQ_PER 4   // NB / SEQ_GROUPS
#define TCH 25      // t-chunk for k2
#define NTCH (TT / TCH)   // 8

typedef unsigned long long u64;

// scratch (device globals; no runtime alloc allowed)
__device__ float g_act[(size_t)NB * ROI * TT * FF];        // (n, roi, t, f)
__device__ float g_xp [(size_t)ROI * TT * NB * G3];        // (roi, t, n, g)

__device__ __forceinline__ u64 pk2(float lo, float hi) {
    u64 r; asm("mov.b64 %0,{%1,%2};" : "=l"(r) : "f"(lo), "f"(hi)); return r;
}
__device__ __forceinline__ void fma2(u64& d, u64 a, u64 b) {
    asm("fma.rn.f32x2 %0,%1,%2,%3;" : "=l"(d) : "l"(a), "l"(b), "l"(d));
}
__device__ __forceinline__ float red2(u64 v) {
    float lo, hi; asm("mov.b64 {%0,%1},%2;" : "=f"(lo), "=f"(hi) : "l"(v));
    return lo + hi;
}
__device__ __forceinline__ float sigmoidf_fast(float x) {
    return __fdividef(1.0f, 1.0f + __expf(-x));
}
__device__ __forceinline__ float tanhf_fast(float x) {
    float e = __expf(2.0f * x);
    return 1.0f - __fdividef(2.0f, e + 1.0f);
}

// ---------------------------------------------------------------------------
// K1 (R3 version): per-(b,t,h, row-half) block
// ---------------------------------------------------------------------------
__global__ __launch_bounds__(288, 2) void k1_agg_mlp(
    const float* __restrict__ x, const float* __restrict__ a,
    const float* __restrict__ eps,
    const float* __restrict__ W1, const float* __restrict__ b1,
    const float* __restrict__ g1, const float* __restrict__ be1,
    const float* __restrict__ W2, const float* __restrict__ b2,
    const float* __restrict__ g2, const float* __restrict__ be2)
{
    extern __shared__ float sm[];
    float* xs  = sm;              // 8640 floats
    float* buf = sm + 8640;       // 4320 floats
    unsigned char* idx8 = (unsigned char*)(sm + 8640 + 4320);  // 45*96 bytes
    int* cnts = (int*)(idx8 + 45 * 96);                        // 45 ints

    const int bid = blockIdx.x;
    const int half = blockIdx.y;
    const int b   = bid / (TT * HH);
    const int rem = bid % (TT * HH);
    const int t   = rem / HH;
    const int hh  = rem % HH;
    const int tid = threadIdx.x;

    {
        const float4* xsrc = (const float4*)x;
        for (int idx = tid; idx < ROI * 24; idx += 288) {
            int i = idx / 24, c4 = idx % 24;
            ((float4*)xs)[i * 24 + c4] =
                xsrc[(((((size_t)b * ROI + i) * TT + t) * HH + hh) * FF) / 4 + c4];
        }
    }

    const int warp = tid >> 5, lane = tid & 31;
    for (int r = warp; r < 45; r += 9) {
        int i = half * 45 + r;
        size_t aoff = ((((size_t)b * ROI + i) * TT + t) * HH + hh) * ROI;
        int cnt = 0;
        #pragma unroll
        for (int c0 = 0; c0 < 96; c0 += 32) {
            int j = c0 + lane;
            float v = (j < ROI) ? a[aoff + j] : 0.0f;
            unsigned m = __ballot_sync(0xffffffffu, v != 0.0f);
            if (v != 0.0f) {
                int pos = cnt + __popc(m & ((1u << lane) - 1u));
                idx8[r * 96 + pos] = (unsigned char)j;
            }
            cnt += __popc(m);
        }
        if (lane == 0) cnts[r] = cnt;
    }
    __syncthreads();

    const float epsv = eps[0];

    {
        const int c4 = tid % 24;
        const int ig = tid / 24;
        for (int r = ig; r < 45; r += 12) {
            int i = half * 45 + r;
            float4 base = ((const float4*)xs)[i * 24 + c4];
            float4 s = make_float4(epsv * base.x, epsv * base.y,
                                   epsv * base.z, epsv * base.w);
            int cnt = cnts[r];
            const unsigned char* il = idx8 + r * 96;
            for (int s0 = 0; s0 < cnt; s0++) {
                int j = il[s0];
                float4 v = ((const float4*)xs)[j * 24 + c4];
                s.x += v.x; s.y += v.y; s.z += v.z; s.w += v.w;
            }
            ((float4*)buf)[r * 24 + c4] = s;
        }
    }
    __syncthreads();

    const int c  = tid % 96;
    const int ib = tid / 96;

    // GEMM1
    {
        u64 acc[15];
        #pragma unroll
        for (int r = 0; r < 15; r++) acc[r] = 0ull;
        for (int k = 0; k < 96; k += 4) {
            float wa = __ldg(&W1[(k + 0) * 96 + c]);
            float wb = __ldg(&W1[(k + 1) * 96 + c]);
            float wc = __ldg(&W1[(k + 2) * 96 + c]);
            float wd = __ldg(&W1[(k + 3) * 96 + c]);
            u64 w01 = pk2(wa, wb), w23 = pk2(wc, wd);
            #pragma unroll
            for (int r = 0; r < 15; r++) {
                ulonglong2 av = *(const ulonglong2*)&buf[(ib + 3 * r) * 96 + k];
                fma2(acc[r], av.x, w01);
                fma2(acc[r], av.y, w23);
            }
        }
        float gs  = g1[c] * rsqrtf(1.0f + 1e-5f);
        float bbv = be1[c];
        float b1c = b1[c];
        __syncthreads();
        #pragma unroll
        for (int r = 0; r < 15; r++) {
            int rr = ib + 3 * r;
            float y = (red2(acc[r]) + b1c) * gs + bbv;
            y = (y > 0.0f) ? y : (__expf(y) - 1.0f);
            xs[rr * 96 + c] = y;
        }
    }
    __syncthreads();

    // GEMM2
    {
        u64 acc[15];
        #pragma unroll
        for (int r = 0; r < 15; r++) acc[r] = 0ull;
        for (int k = 0; k < 96; k += 4) {
            float wa = __ldg(&W2[(k + 0) * 96 + c]);
            float wb = __ldg(&W2[(k + 1) * 96 + c]);
            float wc = __ldg(&W2[(k + 2) * 96 + c]);
            float wd = __ldg(&W2[(k + 3) * 96 + c]);
            u64 w01 = pk2(wa, wb), w23 = pk2(wc, wd);
            #pragma unroll
            for (int r = 0; r < 15; r++) {
                ulonglong2 av = *(const ulonglong2*)&xs[(ib + 3 * r) * 96 + k];
                fma2(acc[r], av.x, w01);
                fma2(acc[r], av.y, w23);
            }
        }
        float gs  = g2[c] * rsqrtf(1.0f + 1e-5f);
        float bbv = be2[c];
        float b2c = b2[c];
        const int n = b * HH + hh;
        #pragma unroll
        for (int r = 0; r < 15; r++) {
            int i = half * 45 + ib + 3 * r;
            float y = (red2(acc[r]) + b2c) * gs + bbv;
            y = fmaxf(y, 0.0f);
            g_act[(((size_t)n * ROI + i) * TT + t) * FF + c] = y;
        }
    }
}

// ---------------------------------------------------------------------------
// K2: GRU input projection, weights register-resident.
//     grid (8, 90): one block per (roi, 25-t chunk). 576 threads = 288 g x 2 kh.
//     Each thread holds its 48-float Wih half-row in 24 u64 regs; per t,
//     12 activation rows are staged and broadcast; kh partials reduced in smem.
// ---------------------------------------------------------------------------
__global__ __launch_bounds__(576, 1) void k2_proj(
    const float* __restrict__ Wih, const float* __restrict__ bih)
{
    __shared__ __align__(16) float acts[NB * 96];    // 12 rows of current t
    __shared__ __align__(16) float part[NB * G3];    // kh=1 partials

    const int roi = blockIdx.y;
    const int t0  = blockIdx.x * TCH;
    const int tid = threadIdx.x;
    const int g   = tid % G3;
    const int kh  = tid / G3;     // 0: k[0,48)  1: k[48,96)

    // load this thread's Wih half-row into registers (once per 300 rows)
    u64 w[24];
    {
        const ulonglong2* wsrc =
            (const ulonglong2*)(Wih + ((size_t)roi * G3 + g) * 96 + kh * 48);
        #pragma unroll
        for (int kk = 0; kk < 12; kk++) {
            ulonglong2 v = __ldg(&wsrc[kk]);
            w[2 * kk + 0] = v.x;
            w[2 * kk + 1] = v.y;
        }
    }
    const float bv = __ldg(&bih[roi * G3 + g]);

    for (int dt = 0; dt < TCH; dt++) {
        const int t = t0 + dt;

        __syncthreads();   // prev iteration's acts/part fully consumed
        // stage 12 rows: acts[n][f] = g_act[n][roi][t][f]
        if (tid < 288) {
            int n = tid / 24, c4 = tid % 24;
            ((float4*)acts)[tid] =
                ((const float4*)g_act)[((((size_t)n * ROI + roi) * TT + t) * FF) / 4 + c4];
        }
        __syncthreads();

        // 12 independent accumulator chains over this kh half
        u64 acc[NB];
        #pragma unroll
        for (int n = 0; n < NB; n++) acc[n] = 0ull;
        #pragma unroll
        for (int kk = 0; kk < 12; kk++) {
            #pragma unroll
            for (int n = 0; n < NB; n++) {
                ulonglong2 av = *(const ulonglong2*)&acts[n * 96 + kh * 48 + 4 * kk];
                fma2(acc[n], av.x, w[2 * kk + 0]);
                fma2(acc[n], av.y, w[2 * kk + 1]);
            }
        }

        if (kh == 1) {
            #pragma unroll
            for (int n = 0; n < NB; n++) part[n * G3 + g] = red2(acc[n]);
        }
        __syncthreads();

        if (kh == 0) {
            float* dst = g_xp + (((size_t)roi * TT + t) * NB) * G3 + g;
            #pragma unroll
            for (int n = 0; n < NB; n++)
                dst[n * G3] = red2(acc[n]) + part[n * G3 + g] + bv;
        }
    }
}

// ---------------------------------------------------------------------------
// K3 (R7 version): grid (90, 3): one block per (roi, 4-seq group).
// ---------------------------------------------------------------------------
__global__ __launch_bounds__(576, 1) void k3_gru(
    const float* __restrict__ Whh, const float* __restrict__ bhh,
    float* __restrict__ out)
{
    __shared__ __align__(16) float hbuf[SEQ_PER * 96];
    __shared__ __align__(16) float rbuf[SEQ_PER * 96];
    __shared__ __align__(16) float zbuf[SEQ_PER * 96];
    __shared__ __align__(16) float hpart[SEQ_PER * G3];

    const int roi = blockIdx.x;
    const int sg  = blockIdx.y;
    const int tid = threadIdx.x;
    const int g   = tid % G3;
    const int kh  = tid / G3;

    u64 wr2[24];
    {
        const ulonglong2* wsrc =
            (const ulonglong2*)(Whh + ((size_t)roi * G3 + g) * 96 + kh * 48);
        #pragma unroll
        for (int kk = 0; kk < 12; kk++) {
            ulonglong2 w = __ldg(&wsrc[kk]);
            wr2[2 * kk + 0] = w.x;
            wr2[2 * kk + 1] = w.y;
        }
    }
    const float bv = __ldg(&bhh[roi * G3 + g]);

    for (int idx = tid; idx < SEQ_PER * 96; idx += 576) hbuf[idx] = 0.0f;
    __syncthreads();

    const int gtype = g / 96;
    const int j     = g % 96;

    for (int t = 0; t < TT; t++) {
        float xv[SEQ_PER];
        if (kh == 0) {
            const float* xpb =
                g_xp + ((((size_t)roi * TT + t) * NB) + sg * SEQ_PER) * G3 + g;
            #pragma unroll
            for (int n = 0; n < SEQ_PER; n++) xv[n] = __ldg(&xpb[n * G3]);
        }

        float hp[SEQ_PER];
        #pragma unroll
        for (int n = 0; n < SEQ_PER; n++) {
            u64 a2 = 0ull;
            const ulonglong2* hrow = (const ulonglong2*)&hbuf[n * 96 + kh * 48];
            #pragma unroll
            for (int kk = 0; kk < 12; kk++) {
                ulonglong2 hv = hrow[kk];
                fma2(a2, hv.x, wr2[2 * kk + 0]);
                fma2(a2, hv.y, wr2[2 * kk + 1]);
            }
            hp[n] = red2(a2);
        }
        if (kh == 1) {
            #pragma unroll
            for (int n = 0; n < SEQ_PER; n++) hpart[n * G3 + g] = hp[n];
        }
        __syncthreads();

        if (kh == 0) {
            #pragma unroll
            for (int n = 0; n < SEQ_PER; n++) hp[n] += hpart[n * G3 + g] + bv;
            if (gtype < 2) {
                float* dst = (gtype == 0) ? rbuf : zbuf;
                #pragma unroll
                for (int n = 0; n < SEQ_PER; n++)
                    dst[n * 96 + j] = sigmoidf_fast(xv[n] + hp[n]);
            }
        }
        __syncthreads();

        if (kh == 0 && gtype == 2) {
            #pragma unroll
            for (int n = 0; n < SEQ_PER; n++) {
                float r  = rbuf[n * 96 + j];
                float z  = zbuf[n * 96 + j];
                float hn = tanhf_fast(xv[n] + r * hp[n]);
                float h0 = hbuf[n * 96 + j];
                float h2 = (1.0f - z) * hn + z * h0;
                hbuf[n * 96 + j] = h2;
                int nn = sg * SEQ_PER + n;
                int b  = nn / HH, hh = nn % HH;
                out[((((size_t)b * ROI + roi) * TT + t) * HH + hh) * 96 + j] = h2;
            }
        }
        __syncthreads();
    }
}

// ---------------------------------------------------------------------------
extern "C" void kernel_launch(void* const* d_in, const int* in_sizes, int n_in,
                              void* d_out, int out_size)
{
    const float* x   = (const float*)d_in[0];
    const float* a   = (const float*)d_in[1];
    const float* eps = (const float*)d_in[2];
    const float* W1  = (const float*)d_in[3];
    const float* b1  = (const float*)d_in[4];
    const float* g1  = (const float*)d_in[5];
    const float* be1 = (const float*)d_in[6];
    const float* W2  = (const float*)d_in[7];
    const float* b2  = (const float*)d_in[8];
    const float* g2  = (const float*)d_in[9];
    const float* be2 = (const float*)d_in[10];
    const float* Wih = (const float*)d_in[11];
    const float* Whh = (const float*)d_in[12];
    const float* bih = (const float*)d_in[13];
    const float* bhh = (const float*)d_in[14];
    float* out = (float*)d_out;

    const int smem1 = (8640 + 4320) * 4 + 45 * 96 + 45 * 4;   // 56,340 B
    cudaFuncSetAttribute(k1_agg_mlp, cudaFuncAttributeMaxDynamicSharedMemorySize, smem1);

    k1_agg_mlp<<<dim3(BB * TT * HH, 2), 288, smem1>>>(x, a, eps, W1, b1, g1, be1,
                                                      W2, b2, g2, be2);
    k2_proj<<<dim3(NTCH, ROI), 576>>>(Wih, bih);
    k3_gru<<<dim3(ROI, SEQ_GROUPS), 576>>>(Whh, bhh, out);
}

// round 9
// speedup vs baseline: 1.0550x; 1.0550x over previous
#include <cuda_runtime.h>

#define BB 4
#define ROI 90
#define TT 200
#define HH 3
#define FF 96
#define G3 288
#define NB 12   // BB*HH
#define SEQ_GROUPS 3
#define SEQ_PER 4   // NB / SEQ_GROUPS
#define TCH 25      // t-chunk for k2
#define NTCH (TT / TCH)   // 8

typedef unsigned long long u64;

// scratch (device globals; no runtime alloc allowed)
__device__ float g_act[(size_t)NB * ROI * TT * FF];        // (n, roi, t, f)
__device__ float g_xp [(size_t)ROI * TT * NB * G3];        // (roi, t, n, g)

__device__ __forceinline__ u64 pk2(float lo, float hi) {
    u64 r; asm("mov.b64 %0,{%1,%2};" : "=l"(r) : "f"(lo), "f"(hi)); return r;
}
__device__ __forceinline__ void fma2(u64& d, u64 a, u64 b) {
    asm("fma.rn.f32x2 %0,%1,%2,%3;" : "=l"(d) : "l"(a), "l"(b), "l"(d));
}
__device__ __forceinline__ float red2(u64 v) {
    float lo, hi; asm("mov.b64 {%0,%1},%2;" : "=f"(lo), "=f"(hi) : "l"(v));
    return lo + hi;
}
__device__ __forceinline__ float sigmoidf_fast(float x) {
    return __fdividef(1.0f, 1.0f + __expf(-x));
}
__device__ __forceinline__ float tanhf_fast(float x) {
    float e = __expf(2.0f * x);
    return 1.0f - __fdividef(2.0f, e + 1.0f);
}

// ---------------------------------------------------------------------------
// K1 (R3 version, proven): per-(b,t,h, row-half) block
// ---------------------------------------------------------------------------
__global__ __launch_bounds__(288, 2) void k1_agg_mlp(
    const float* __restrict__ x, const float* __restrict__ a,
    const float* __restrict__ eps,
    const float* __restrict__ W1, const float* __restrict__ b1,
    const float* __restrict__ g1, const float* __restrict__ be1,
    const float* __restrict__ W2, const float* __restrict__ b2,
    const float* __restrict__ g2, const float* __restrict__ be2)
{
    extern __shared__ float sm[];
    float* xs  = sm;              // 8640 floats
    float* buf = sm + 8640;       // 4320 floats
    unsigned char* idx8 = (unsigned char*)(sm + 8640 + 4320);  // 45*96 bytes
    int* cnts = (int*)(idx8 + 45 * 96);                        // 45 ints

    const int bid = blockIdx.x;
    const int half = blockIdx.y;
    const int b   = bid / (TT * HH);
    const int rem = bid % (TT * HH);
    const int t   = rem / HH;
    const int hh  = rem % HH;
    const int tid = threadIdx.x;

    {
        const float4* xsrc = (const float4*)x;
        for (int idx = tid; idx < ROI * 24; idx += 288) {
            int i = idx / 24, c4 = idx % 24;
            ((float4*)xs)[i * 24 + c4] =
                xsrc[(((((size_t)b * ROI + i) * TT + t) * HH + hh) * FF) / 4 + c4];
        }
    }

    const int warp = tid >> 5, lane = tid & 31;
    for (int r = warp; r < 45; r += 9) {
        int i = half * 45 + r;
        size_t aoff = ((((size_t)b * ROI + i) * TT + t) * HH + hh) * ROI;
        int cnt = 0;
        #pragma unroll
        for (int c0 = 0; c0 < 96; c0 += 32) {
            int j = c0 + lane;
            float v = (j < ROI) ? a[aoff + j] : 0.0f;
            unsigned m = __ballot_sync(0xffffffffu, v != 0.0f);
            if (v != 0.0f) {
                int pos = cnt + __popc(m & ((1u << lane) - 1u));
                idx8[r * 96 + pos] = (unsigned char)j;
            }
            cnt += __popc(m);
        }
        if (lane == 0) cnts[r] = cnt;
    }
    __syncthreads();

    const float epsv = eps[0];

    {
        const int c4 = tid % 24;
        const int ig = tid / 24;
        for (int r = ig; r < 45; r += 12) {
            int i = half * 45 + r;
            float4 base = ((const float4*)xs)[i * 24 + c4];
            float4 s = make_float4(epsv * base.x, epsv * base.y,
                                   epsv * base.z, epsv * base.w);
            int cnt = cnts[r];
            const unsigned char* il = idx8 + r * 96;
            for (int s0 = 0; s0 < cnt; s0++) {
                int j = il[s0];
                float4 v = ((const float4*)xs)[j * 24 + c4];
                s.x += v.x; s.y += v.y; s.z += v.z; s.w += v.w;
            }
            ((float4*)buf)[r * 24 + c4] = s;
        }
    }
    __syncthreads();

    const int c  = tid % 96;
    const int ib = tid / 96;

    // GEMM1
    {
        u64 acc[15];
        #pragma unroll
        for (int r = 0; r < 15; r++) acc[r] = 0ull;
        for (int k = 0; k < 96; k += 4) {
            float wa = __ldg(&W1[(k + 0) * 96 + c]);
            float wb = __ldg(&W1[(k + 1) * 96 + c]);
            float wc = __ldg(&W1[(k + 2) * 96 + c]);
            float wd = __ldg(&W1[(k + 3) * 96 + c]);
            u64 w01 = pk2(wa, wb), w23 = pk2(wc, wd);
            #pragma unroll
            for (int r = 0; r < 15; r++) {
                ulonglong2 av = *(const ulonglong2*)&buf[(ib + 3 * r) * 96 + k];
                fma2(acc[r], av.x, w01);
                fma2(acc[r], av.y, w23);
            }
        }
        float gs  = g1[c] * rsqrtf(1.0f + 1e-5f);
        float bbv = be1[c];
        float b1c = b1[c];
        __syncthreads();
        #pragma unroll
        for (int r = 0; r < 15; r++) {
            int rr = ib + 3 * r;
            float y = (red2(acc[r]) + b1c) * gs + bbv;
            y = (y > 0.0f) ? y : (__expf(y) - 1.0f);
            xs[rr * 96 + c] = y;
        }
    }
    __syncthreads();

    // GEMM2
    {
        u64 acc[15];
        #pragma unroll
        for (int r = 0; r < 15; r++) acc[r] = 0ull;
        for (int k = 0; k < 96; k += 4) {
            float wa = __ldg(&W2[(k + 0) * 96 + c]);
            float wb = __ldg(&W2[(k + 1) * 96 + c]);
            float wc = __ldg(&W2[(k + 2) * 96 + c]);
            float wd = __ldg(&W2[(k + 3) * 96 + c]);
            u64 w01 = pk2(wa, wb), w23 = pk2(wc, wd);
            #pragma unroll
            for (int r = 0; r < 15; r++) {
                ulonglong2 av = *(const ulonglong2*)&xs[(ib + 3 * r) * 96 + k];
                fma2(acc[r], av.x, w01);
                fma2(acc[r], av.y, w23);
            }
        }
        float gs  = g2[c] * rsqrtf(1.0f + 1e-5f);
        float bbv = be2[c];
        float b2c = b2[c];
        const int n = b * HH + hh;
        #pragma unroll
        for (int r = 0; r < 15; r++) {
            int i = half * 45 + ib + 3 * r;
            float y = (red2(acc[r]) + b2c) * gs + bbv;
            y = fmaxf(y, 0.0f);
            g_act[(((size_t)n * ROI + i) * TT + t) * FF + c] = y;
        }
    }
}

// ---------------------------------------------------------------------------
// K2: register-resident weights + software-pipelined staging.
//     grid (8, 90); 576 threads = 288 g x 2 kh; ONE barrier per time step.
// ---------------------------------------------------------------------------
__global__ __launch_bounds__(576, 1) void k2_proj(
    const float* __restrict__ Wih, const float* __restrict__ bih)
{
    __shared__ __align__(16) float acts[2][NB * 96];   // double-buffered rows
    __shared__ __align__(16) float part[2][NB * G3];   // double-buffered partials

    const int roi = blockIdx.y;
    const int t0  = blockIdx.x * TCH;
    const int tid = threadIdx.x;
    const int g   = tid % G3;
    const int kh  = tid / G3;     // 0: k[0,48)  1: k[48,96)

    // Wih half-row in registers (reused for 300 output rows)
    u64 w[24];
    {
        const ulonglong2* wsrc =
            (const ulonglong2*)(Wih + ((size_t)roi * G3 + g) * 96 + kh * 48);
        #pragma unroll
        for (int kk = 0; kk < 12; kk++) {
            ulonglong2 v = __ldg(&wsrc[kk]);
            w[2 * kk + 0] = v.x;
            w[2 * kk + 1] = v.y;
        }
    }
    const float bv = __ldg(&bih[roi * G3 + g]);

    // prologue: stage t0 into buffer 0
    const int sn = tid / 24, sc4 = tid % 24;   // staging row/col for tid<288
    if (tid < 288) {
        ((float4*)acts[0])[tid] =
            ((const float4*)g_act)[((((size_t)sn * ROI + roi) * TT + t0) * FF) / 4 + sc4];
    }
    __syncthreads();

    for (int dt = 0; dt < TCH; dt++) {
        const int t   = t0 + dt;
        const int cur = dt & 1, nxt = cur ^ 1;

        // prefetch next step's rows into registers (issues early, lands late)
        float4 pf;
        const bool havepf = (tid < 288) && (dt + 1 < TCH);
        if (havepf) {
            pf = __ldg(&((const float4*)g_act)
                 [((((size_t)sn * ROI + roi) * TT + (t + 1)) * FF) / 4 + sc4]);
        }

        // 12 independent accumulator chains over this kh half
        u64 acc[NB];
        #pragma unroll
        for (int n = 0; n < NB; n++) acc[n] = 0ull;
        #pragma unroll
        for (int kk = 0; kk < 12; kk++) {
            #pragma unroll
            for (int n = 0; n < NB; n++) {
                ulonglong2 av = *(const ulonglong2*)&acts[cur][n * 96 + kh * 48 + 4 * kk];
                fma2(acc[n], av.x, w[2 * kk + 0]);
                fma2(acc[n], av.y, w[2 * kk + 1]);
            }
        }

        if (kh == 1) {
            #pragma unroll
            for (int n = 0; n < NB; n++) part[cur][n * G3 + g] = red2(acc[n]);
        }
        if (havepf) ((float4*)acts[nxt])[tid] = pf;
        __syncthreads();   // the only barrier per step

        if (kh == 0) {
            float* dst = g_xp + (((size_t)roi * TT + t) * NB) * G3 + g;
            #pragma unroll
            for (int n = 0; n < NB; n++)
                dst[n * G3] = red2(acc[n]) + part[cur][n * G3 + g] + bv;
        }
    }
}

// ---------------------------------------------------------------------------
// K3 (R7 + xv prefetch): grid (90, 3): one block per (roi, 4-seq group).
// ---------------------------------------------------------------------------
__global__ __launch_bounds__(576, 1) void k3_gru(
    const float* __restrict__ Whh, const float* __restrict__ bhh,
    float* __restrict__ out)
{
    __shared__ __align__(16) float hbuf[SEQ_PER * 96];
    __shared__ __align__(16) float rbuf[SEQ_PER * 96];
    __shared__ __align__(16) float zbuf[SEQ_PER * 96];
    __shared__ __align__(16) float hpart[SEQ_PER * G3];

    const int roi = blockIdx.x;
    const int sg  = blockIdx.y;
    const int tid = threadIdx.x;
    const int g   = tid % G3;
    const int kh  = tid / G3;

    u64 wr2[24];
    {
        const ulonglong2* wsrc =
            (const ulonglong2*)(Whh + ((size_t)roi * G3 + g) * 96 + kh * 48);
        #pragma unroll
        for (int kk = 0; kk < 12; kk++) {
            ulonglong2 w = __ldg(&wsrc[kk]);
            wr2[2 * kk + 0] = w.x;
            wr2[2 * kk + 1] = w.y;
        }
    }
    const float bv = __ldg(&bhh[roi * G3 + g]);

    for (int idx = tid; idx < SEQ_PER * 96; idx += 576) hbuf[idx] = 0.0f;

    const int gtype = g / 96;
    const int j     = g % 96;
    const float* xpbase =
        g_xp + (((size_t)roi * TT) * NB + sg * SEQ_PER) * G3 + g;

    // prefetch t=0 xv
    float xvn[SEQ_PER];
    if (kh == 0) {
        #pragma unroll
        for (int n = 0; n < SEQ_PER; n++)
            xvn[n] = __ldg(&xpbase[(size_t)n * G3]);
    }
    __syncthreads();

    for (int t = 0; t < TT; t++) {
        float xv[SEQ_PER];
        if (kh == 0) {
            #pragma unroll
            for (int n = 0; n < SEQ_PER; n++) xv[n] = xvn[n];
            if (t + 1 < TT) {
                const float* nb2 = xpbase + (size_t)(t + 1) * NB * G3;
                #pragma unroll
                for (int n = 0; n < SEQ_PER; n++)
                    xvn[n] = __ldg(&nb2[(size_t)n * G3]);
            }
        }

        float hp[SEQ_PER];
        #pragma unroll
        for (int n = 0; n < SEQ_PER; n++) {
            u64 a2 = 0ull;
            const ulonglong2* hrow = (const ulonglong2*)&hbuf[n * 96 + kh * 48];
            #pragma unroll
            for (int kk = 0; kk < 12; kk++) {
                ulonglong2 hv = hrow[kk];
                fma2(a2, hv.x, wr2[2 * kk + 0]);
                fma2(a2, hv.y, wr2[2 * kk + 1]);
            }
            hp[n] = red2(a2);
        }
        if (kh == 1) {
            #pragma unroll
            for (int n = 0; n < SEQ_PER; n++) hpart[n * G3 + g] = hp[n];
        }
        __syncthreads();

        if (kh == 0) {
            #pragma unroll
            for (int n = 0; n < SEQ_PER; n++) hp[n] += hpart[n * G3 + g] + bv;
            if (gtype < 2) {
                float* dst = (gtype == 0) ? rbuf : zbuf;
                #pragma unroll
                for (int n = 0; n < SEQ_PER; n++)
                    dst[n * 96 + j] = sigmoidf_fast(xv[n] + hp[n]);
            }
        }
        __syncthreads();

        if (kh == 0 && gtype == 2) {
            #pragma unroll
            for (int n = 0; n < SEQ_PER; n++) {
                float r  = rbuf[n * 96 + j];
                float z  = zbuf[n * 96 + j];
                float hn = tanhf_fast(xv[n] + r * hp[n]);
                float h0 = hbuf[n * 96 + j];
                float h2 = (1.0f - z) * hn + z * h0;
                hbuf[n * 96 + j] = h2;
                int nn = sg * SEQ_PER + n;
                int b  = nn / HH, hh = nn % HH;
                out[((((size_t)b * ROI + roi) * TT + t) * HH + hh) * 96 + j] = h2;
            }
        }
        __syncthreads();
    }
}

// ---------------------------------------------------------------------------
extern "C" void kernel_launch(void* const* d_in, const int* in_sizes, int n_in,
                              void* d_out, int out_size)
{
    const float* x   = (const float*)d_in[0];
    const float* a   = (const float*)d_in[1];
    const float* eps = (const float*)d_in[2];
    const float* W1  = (const float*)d_in[3];
    const float* b1  = (const float*)d_in[4];
    const float* g1  = (const float*)d_in[5];
    const float* be1 = (const float*)d_in[6];
    const float* W2  = (const float*)d_in[7];
    const float* b2  = (const float*)d_in[8];
    const float* g2  = (const float*)d_in[9];
    const float* be2 = (const float*)d_in[10];
    const float* Wih = (const float*)d_in[11];
    const float* Whh = (const float*)d_in[12];
    const float* bih = (const float*)d_in[13];
    const float* bhh = (const float*)d_in[14];
    float* out = (float*)d_out;

    const int smem1 = (8640 + 4320) * 4 + 45 * 96 + 45 * 4;   // 56,340 B
    cudaFuncSetAttribute(k1_agg_mlp, cudaFuncAttributeMaxDynamicSharedMemorySize, smem1);

    k1_agg_mlp<<<dim3(BB * TT * HH, 2), 288, smem1>>>(x, a, eps, W1, b1, g1, be1,
                                                      W2, b2, g2, be2);
    k2_proj<<<dim3(NTCH, ROI), 576>>>(Wih, bih);
    k3_gru<<<dim3(ROI, SEQ_GROUPS), 576>>>(Whh, bhh, out);
}

// round 10
// speedup vs baseline: 1.1163x; 1.0580x over previous
#include <cuda_runtime.h>

#define BB 4
#define ROI 90
#define TT 200
#define HH 3
#define FF 96
#define G3 288
#define NB 12   // BB*HH
#define SEQ_GROUPS 3
#define SEQ_PER 4   // NB / SEQ_GROUPS
#define TCH 25      // t-chunk for k2
#define NTCH (TT / TCH)   // 8

typedef unsigned long long u64;

// scratch (device globals; no runtime alloc allowed)
__device__ float g_act[(size_t)NB * ROI * TT * FF];        // (n, roi, t, f)
__device__ float g_xp [(size_t)ROI * TT * NB * G3];        // (roi, t, n, g)

__device__ __forceinline__ u64 pk2(float lo, float hi) {
    u64 r; asm("mov.b64 %0,{%1,%2};" : "=l"(r) : "f"(lo), "f"(hi)); return r;
}
__device__ __forceinline__ void fma2(u64& d, u64 a, u64 b) {
    asm("fma.rn.f32x2 %0,%1,%2,%3;" : "=l"(d) : "l"(a), "l"(b), "l"(d));
}
__device__ __forceinline__ float red2(u64 v) {
    float lo, hi; asm("mov.b64 {%0,%1},%2;" : "=f"(lo), "=f"(hi) : "l"(v));
    return lo + hi;
}
__device__ __forceinline__ float sigmoidf_fast(float x) {
    return __fdividef(1.0f, 1.0f + __expf(-x));
}
__device__ __forceinline__ float tanhf_fast(float x) {
    float e = __expf(2.0f * x);
    return 1.0f - __fdividef(2.0f, e + 1.0f);
}

// ---------------------------------------------------------------------------
// K1: per-(b,t,h, row-half) block. R3 structure, but register cap ≤75
//     (__launch_bounds__(288,3)) so 3 blocks fit per SM instead of 2.
// ---------------------------------------------------------------------------
__global__ __launch_bounds__(288, 3) void k1_agg_mlp(
    const float* __restrict__ x, const float* __restrict__ a,
    const float* __restrict__ eps,
    const float* __restrict__ W1, const float* __restrict__ b1,
    const float* __restrict__ g1, const float* __restrict__ be1,
    const float* __restrict__ W2, const float* __restrict__ b2,
    const float* __restrict__ g2, const float* __restrict__ be2)
{
    extern __shared__ float sm[];
    float* xs  = sm;              // 8640 floats
    float* buf = sm + 8640;       // 4320 floats
    unsigned char* idx8 = (unsigned char*)(sm + 8640 + 4320);  // 45*96 bytes
    int* cnts = (int*)(idx8 + 45 * 96);                        // 45 ints

    const int bid = blockIdx.x;
    const int half = blockIdx.y;
    const int b   = bid / (TT * HH);
    const int rem = bid % (TT * HH);
    const int t   = rem / HH;
    const int hh  = rem % HH;
    const int tid = threadIdx.x;

    {
        const float4* xsrc = (const float4*)x;
        for (int idx = tid; idx < ROI * 24; idx += 288) {
            int i = idx / 24, c4 = idx % 24;
            ((float4*)xs)[i * 24 + c4] =
                xsrc[(((((size_t)b * ROI + i) * TT + t) * HH + hh) * FF) / 4 + c4];
        }
    }

    const int warp = tid >> 5, lane = tid & 31;
    for (int r = warp; r < 45; r += 9) {
        int i = half * 45 + r;
        size_t aoff = ((((size_t)b * ROI + i) * TT + t) * HH + hh) * ROI;
        int cnt = 0;
        #pragma unroll
        for (int c0 = 0; c0 < 96; c0 += 32) {
            int j = c0 + lane;
            float v = (j < ROI) ? a[aoff + j] : 0.0f;
            unsigned m = __ballot_sync(0xffffffffu, v != 0.0f);
            if (v != 0.0f) {
                int pos = cnt + __popc(m & ((1u << lane) - 1u));
                idx8[r * 96 + pos] = (unsigned char)j;
            }
            cnt += __popc(m);
        }
        if (lane == 0) cnts[r] = cnt;
    }
    __syncthreads();

    const float epsv = eps[0];

    {
        const int c4 = tid % 24;
        const int ig = tid / 24;
        for (int r = ig; r < 45; r += 12) {
            int i = half * 45 + r;
            float4 base = ((const float4*)xs)[i * 24 + c4];
            float4 s = make_float4(epsv * base.x, epsv * base.y,
                                   epsv * base.z, epsv * base.w);
            int cnt = cnts[r];
            const unsigned char* il = idx8 + r * 96;
            for (int s0 = 0; s0 < cnt; s0++) {
                int j = il[s0];
                float4 v = ((const float4*)xs)[j * 24 + c4];
                s.x += v.x; s.y += v.y; s.z += v.z; s.w += v.w;
            }
            ((float4*)buf)[r * 24 + c4] = s;
        }
    }
    __syncthreads();

    const int c  = tid % 96;
    const int ib = tid / 96;

    // GEMM1
    {
        u64 acc[15];
        #pragma unroll
        for (int r = 0; r < 15; r++) acc[r] = 0ull;
        #pragma unroll 2
        for (int k = 0; k < 96; k += 4) {
            float wa = __ldg(&W1[(k + 0) * 96 + c]);
            float wb = __ldg(&W1[(k + 1) * 96 + c]);
            float wc = __ldg(&W1[(k + 2) * 96 + c]);
            float wd = __ldg(&W1[(k + 3) * 96 + c]);
            u64 w01 = pk2(wa, wb), w23 = pk2(wc, wd);
            #pragma unroll
            for (int r = 0; r < 15; r++) {
                ulonglong2 av = *(const ulonglong2*)&buf[(ib + 3 * r) * 96 + k];
                fma2(acc[r], av.x, w01);
                fma2(acc[r], av.y, w23);
            }
        }
        float gs  = g1[c] * rsqrtf(1.0f + 1e-5f);
        float bbv = be1[c];
        float b1c = b1[c];
        __syncthreads();
        #pragma unroll
        for (int r = 0; r < 15; r++) {
            int rr = ib + 3 * r;
            float y = (red2(acc[r]) + b1c) * gs + bbv;
            y = (y > 0.0f) ? y : (__expf(y) - 1.0f);
            xs[rr * 96 + c] = y;
        }
    }
    __syncthreads();

    // GEMM2
    {
        u64 acc[15];
        #pragma unroll
        for (int r = 0; r < 15; r++) acc[r] = 0ull;
        #pragma unroll 2
        for (int k = 0; k < 96; k += 4) {
            float wa = __ldg(&W2[(k + 0) * 96 + c]);
            float wb = __ldg(&W2[(k + 1) * 96 + c]);
            float wc = __ldg(&W2[(k + 2) * 96 + c]);
            float wd = __ldg(&W2[(k + 3) * 96 + c]);
            u64 w01 = pk2(wa, wb), w23 = pk2(wc, wd);
            #pragma unroll
            for (int r = 0; r < 15; r++) {
                ulonglong2 av = *(const ulonglong2*)&xs[(ib + 3 * r) * 96 + k];
                fma2(acc[r], av.x, w01);
                fma2(acc[r], av.y, w23);
            }
        }
        float gs  = g2[c] * rsqrtf(1.0f + 1e-5f);
        float bbv = be2[c];
        float b2c = b2[c];
        const int n = b * HH + hh;
        #pragma unroll
        for (int r = 0; r < 15; r++) {
            int i = half * 45 + ib + 3 * r;
            float y = (red2(acc[r]) + b2c) * gs + bbv;
            y = fmaxf(y, 0.0f);
            g_act[(((size_t)n * ROI + i) * TT + t) * FF + c] = y;
        }
    }
}

// ---------------------------------------------------------------------------
// K2 (R9 version): register-resident weights + software-pipelined staging.
// ---------------------------------------------------------------------------
__global__ __launch_bounds__(576, 1) void k2_proj(
    const float* __restrict__ Wih, const float* __restrict__ bih)
{
    __shared__ __align__(16) float acts[2][NB * 96];
    __shared__ __align__(16) float part[2][NB * G3];

    const int roi = blockIdx.y;
    const int t0  = blockIdx.x * TCH;
    const int tid = threadIdx.x;
    const int g   = tid % G3;
    const int kh  = tid / G3;

    u64 w[24];
    {
        const ulonglong2* wsrc =
            (const ulonglong2*)(Wih + ((size_t)roi * G3 + g) * 96 + kh * 48);
        #pragma unroll
        for (int kk = 0; kk < 12; kk++) {
            ulonglong2 v = __ldg(&wsrc[kk]);
            w[2 * kk + 0] = v.x;
            w[2 * kk + 1] = v.y;
        }
    }
    const float bv = __ldg(&bih[roi * G3 + g]);

    const int sn = tid / 24, sc4 = tid % 24;
    if (tid < 288) {
        ((float4*)acts[0])[tid] =
            ((const float4*)g_act)[((((size_t)sn * ROI + roi) * TT + t0) * FF) / 4 + sc4];
    }
    __syncthreads();

    for (int dt = 0; dt < TCH; dt++) {
        const int t   = t0 + dt;
        const int cur = dt & 1, nxt = cur ^ 1;

        float4 pf;
        const bool havepf = (tid < 288) && (dt + 1 < TCH);
        if (havepf) {
            pf = __ldg(&((const float4*)g_act)
                 [((((size_t)sn * ROI + roi) * TT + (t + 1)) * FF) / 4 + sc4]);
        }

        u64 acc[NB];
        #pragma unroll
        for (int n = 0; n < NB; n++) acc[n] = 0ull;
        #pragma unroll
        for (int kk = 0; kk < 12; kk++) {
            #pragma unroll
            for (int n = 0; n < NB; n++) {
                ulonglong2 av = *(const ulonglong2*)&acts[cur][n * 96 + kh * 48 + 4 * kk];
                fma2(acc[n], av.x, w[2 * kk + 0]);
                fma2(acc[n], av.y, w[2 * kk + 1]);
            }
        }

        if (kh == 1) {
            #pragma unroll
            for (int n = 0; n < NB; n++) part[cur][n * G3 + g] = red2(acc[n]);
        }
        if (havepf) ((float4*)acts[nxt])[tid] = pf;
        __syncthreads();

        if (kh == 0) {
            float* dst = g_xp + (((size_t)roi * TT + t) * NB) * G3 + g;
            #pragma unroll
            for (int n = 0; n < NB; n++)
                dst[n * G3] = red2(acc[n]) + part[cur][n * G3 + g] + bv;
        }
    }
}

// ---------------------------------------------------------------------------
// K3 (R9 version): grid (90, 3), xv prefetch.
// ---------------------------------------------------------------------------
__global__ __launch_bounds__(576, 1) void k3_gru(
    const float* __restrict__ Whh, const float* __restrict__ bhh,
    float* __restrict__ out)
{
    __shared__ __align__(16) float hbuf[SEQ_PER * 96];
    __shared__ __align__(16) float rbuf[SEQ_PER * 96];
    __shared__ __align__(16) float zbuf[SEQ_PER * 96];
    __shared__ __align__(16) float hpart[SEQ_PER * G3];

    const int roi = blockIdx.x;
    const int sg  = blockIdx.y;
    const int tid = threadIdx.x;
    const int g   = tid % G3;
    const int kh  = tid / G3;

    u64 wr2[24];
    {
        const ulonglong2* wsrc =
            (const ulonglong2*)(Whh + ((size_t)roi * G3 + g) * 96 + kh * 48);
        #pragma unroll
        for (int kk = 0; kk < 12; kk++) {
            ulonglong2 w = __ldg(&wsrc[kk]);
            wr2[2 * kk + 0] = w.x;
            wr2[2 * kk + 1] = w.y;
        }
    }
    const float bv = __ldg(&bhh[roi * G3 + g]);

    for (int idx = tid; idx < SEQ_PER * 96; idx += 576) hbuf[idx] = 0.0f;

    const int gtype = g / 96;
    const int j     = g % 96;
    const float* xpbase =
        g_xp + (((size_t)roi * TT) * NB + sg * SEQ_PER) * G3 + g;

    float xvn[SEQ_PER];
    if (kh == 0) {
        #pragma unroll
        for (int n = 0; n < SEQ_PER; n++)
            xvn[n] = __ldg(&xpbase[(size_t)n * G3]);
    }
    __syncthreads();

    for (int t = 0; t < TT; t++) {
        float xv[SEQ_PER];
        if (kh == 0) {
            #pragma unroll
            for (int n = 0; n < SEQ_PER; n++) xv[n] = xvn[n];
            if (t + 1 < TT) {
                const float* nb2 = xpbase + (size_t)(t + 1) * NB * G3;
                #pragma unroll
                for (int n = 0; n < SEQ_PER; n++)
                    xvn[n] = __ldg(&nb2[(size_t)n * G3]);
            }
        }

        float hp[SEQ_PER];
        #pragma unroll
        for (int n = 0; n < SEQ_PER; n++) {
            u64 a2 = 0ull;
            const ulonglong2* hrow = (const ulonglong2*)&hbuf[n * 96 + kh * 48];
            #pragma unroll
            for (int kk = 0; kk < 12; kk++) {
                ulonglong2 hv = hrow[kk];
                fma2(a2, hv.x, wr2[2 * kk + 0]);
                fma2(a2, hv.y, wr2[2 * kk + 1]);
            }
            hp[n] = red2(a2);
        }
        if (kh == 1) {
            #pragma unroll
            for (int n = 0; n < SEQ_PER; n++) hpart[n * G3 + g] = hp[n];
        }
        __syncthreads();

        if (kh == 0) {
            #pragma unroll
            for (int n = 0; n < SEQ_PER; n++) hp[n] += hpart[n * G3 + g] + bv;
            if (gtype < 2) {
                float* dst = (gtype == 0) ? rbuf : zbuf;
                #pragma unroll
                for (int n = 0; n < SEQ_PER; n++)
                    dst[n * 96 + j] = sigmoidf_fast(xv[n] + hp[n]);
            }
        }
        __syncthreads();

        if (kh == 0 && gtype == 2) {
            #pragma unroll
            for (int n = 0; n < SEQ_PER; n++) {
                float r  = rbuf[n * 96 + j];
                float z  = zbuf[n * 96 + j];
                float hn = tanhf_fast(xv[n] + r * hp[n]);
                float h0 = hbuf[n * 96 + j];
                float h2 = (1.0f - z) * hn + z * h0;
                hbuf[n * 96 + j] = h2;
                int nn = sg * SEQ_PER + n;
                int b  = nn / HH, hh = nn % HH;
                out[((((size_t)b * ROI + roi) * TT + t) * HH + hh) * 96 + j] = h2;
            }
        }
        __syncthreads();
    }
}

// ---------------------------------------------------------------------------
extern "C" void kernel_launch(void* const* d_in, const int* in_sizes, int n_in,
                              void* d_out, int out_size)
{
    const float* x   = (const float*)d_in[0];
    const float* a   = (const float*)d_in[1];
    const float* eps = (const float*)d_in[2];
    const float* W1  = (const float*)d_in[3];
    const float* b1  = (const float*)d_in[4];
    const float* g1  = (const float*)d_in[5];
    const float* be1 = (const float*)d_in[6];
    const float* W2  = (const float*)d_in[7];
    const float* b2  = (const float*)d_in[8];
    const float* g2  = (const float*)d_in[9];
    const float* be2 = (const float*)d_in[10];
    const float* Wih = (const float*)d_in[11];
    const float* Whh = (const float*)d_in[12];
    const float* bih = (const float*)d_in[13];
    const float* bhh = (const float*)d_in[14];
    float* out = (float*)d_out;

    const int smem1 = (8640 + 4320) * 4 + 45 * 96 + 45 * 4;   // 56,340 B
    cudaFuncSetAttribute(k1_agg_mlp, cudaFuncAttributeMaxDynamicSharedMemorySize, smem1);

    k1_agg_mlp<<<dim3(BB * TT * HH, 2), 288, smem1>>>(x, a, eps, W1, b1, g1, be1,
                                                      W2, b2, g2, be2);
    k2_proj<<<dim3(NTCH, ROI), 576>>>(Wih, bih);
    k3_gru<<<dim3(ROI, SEQ_GROUPS), 576>>>(Whh, bhh, out);
}